// round 2
// baseline (speedup 1.0000x reference)
#include <cuda_runtime.h>
#include <math.h>

#define BATCH 4
#define SEQ   8192
#define CH    768
#define N2    4096
#define MODES 4097
#define NBLK  8
#define BLK   96
#define LAM   0.01f

#define FWD_SCALE 0.011048543456039806f   // 1/sqrt(8192)
#define INV_SCALE 0.022097086912079613f   // sqrt(8192)/4096

// ---------------- device scratch ----------------
__device__ float  g_Xre[BATCH * CH * MODES];
__device__ float  g_Xim[BATCH * CH * MODES];
__device__ float  g_yT [BATCH * CH * SEQ];
__device__ float2 g_wfft[N2];     // exp(-2*pi*i*t/4096)
__device__ float2 g_wr  [MODES];  // (cos,sin)(2*pi*k/8192)

// ---------------- tables ----------------
__global__ void init_tables_kernel() {
    int i = blockIdx.x * blockDim.x + threadIdx.x;
    if (i < N2) {
        float s, c;
        sincospif((float)i * (1.0f / 2048.0f), &s, &c);
        g_wfft[i] = make_float2(c, -s);
    }
    if (i < MODES) {
        float s, c;
        sincospif((float)i * (1.0f / 4096.0f), &s, &c);
        g_wr[i] = make_float2(c, s);
    }
}

// ---------------- complex helpers ----------------
__device__ __forceinline__ float2 cadd(float2 a, float2 b) { return make_float2(a.x + b.x, a.y + b.y); }
__device__ __forceinline__ float2 csub(float2 a, float2 b) { return make_float2(a.x - b.x, a.y - b.y); }
__device__ __forceinline__ float2 cmul(float2 a, float2 b) {
    return make_float2(fmaf(a.x, b.x, -a.y * b.y), fmaf(a.x, b.y, a.y * b.x));
}

// ---------------- 4096-pt radix-4 Stockham (forward, e^{-i}) ----------------
// Natural-order output. 6 stages; result pointer returned. Caller must have
// synced after filling A. Internally syncs after each stage.
__device__ float2* fft4096(float2* A, float2* B) {
    float2* src = A;
    float2* dst = B;
    int ls = 0;  // log2(sstr); sstr = 4096/n
    #pragma unroll
    for (int stage = 0; stage < 6; stage++) {
        int m = 1024 >> (2 * stage);
        for (int idx = threadIdx.x; idx < 1024; idx += 256) {
            int q = idx & ((1 << ls) - 1);
            int p = idx >> ls;
            float2 a = src[q + ((p        ) << ls)];
            float2 b = src[q + ((p +     m) << ls)];
            float2 c = src[q + ((p + 2 * m) << ls)];
            float2 d = src[q + ((p + 3 * m) << ls)];
            float2 apc = cadd(a, c), amc = csub(a, c);
            float2 bpd = cadd(b, d), bmd = csub(b, d);
            int tw = p << ls;  // p * sstr
            float2 w1 = g_wfft[tw];
            float2 w2 = g_wfft[2 * tw];
            float2 w3 = g_wfft[3 * tw];
            // y1 = w1*(amc - i*bmd), y3 = w3*(amc + i*bmd)
            float2 t1 = make_float2(amc.x + bmd.y, amc.y - bmd.x);
            float2 t3 = make_float2(amc.x - bmd.y, amc.y + bmd.x);
            dst[q + ((4 * p + 0) << ls)] = cadd(apc, bpd);
            dst[q + ((4 * p + 1) << ls)] = cmul(w1, t1);
            dst[q + ((4 * p + 2) << ls)] = cmul(w2, csub(apc, bpd));
            dst[q + ((4 * p + 3) << ls)] = cmul(w3, t3);
        }
        __syncthreads();
        float2* t = src; src = dst; dst = t;
        ls += 2;
    }
    return src;
}

// ---------------- forward rfft: x[b,s,c] -> X planar [b*CH+c][k] ----------------
__global__ void __launch_bounds__(256) fwd_fft_kernel(const float* __restrict__ x) {
    extern __shared__ char smraw[];
    float2* A = (float2*)smraw;
    float2* B = A + 4096;
    int row = blockIdx.x;                 // b*CH + c
    int b = row / CH, c = row % CH;
    const float* xr = x + ((size_t)b * SEQ) * CH + c;
    for (int j = threadIdx.x; j < 4096; j += 256) {
        A[j] = make_float2(xr[(size_t)(2 * j) * CH], xr[(size_t)(2 * j + 1) * CH]);
    }
    __syncthreads();
    float2* R = fft4096(A, B);
    float* Xre = g_Xre + (size_t)row * MODES;
    float* Xim = g_Xim + (size_t)row * MODES;
    for (int k = threadIdx.x; k <= 4096; k += 256) {
        float2 Zk = R[k & 4095];
        float2 Zc = R[(4096 - k) & 4095];
        float Ex = 0.5f * (Zk.x + Zc.x), Ey = 0.5f * (Zk.y - Zc.y);
        float Ox = 0.5f * (Zk.x - Zc.x), Oy = 0.5f * (Zk.y + Zc.y);
        float2 w = g_wr[k];
        // X = E + W^k * O,  W^k = (c,-s),  O = -i*Od
        float re = Ex + w.x * Oy - w.y * Ox;
        float im = Ey - w.x * Ox - w.y * Oy;
        Xre[k] = FWD_SCALE * re;
        Xim[k] = FWD_SCALE * im;
    }
}

// ---------------- block-diagonal complex 2-layer MLP on modes ----------------
#define KT 64
#define MLP_SMEM ((4 * 9216 + 384 + 2 * 6144) * 4)

__global__ void __launch_bounds__(256) mlp_kernel(const float* __restrict__ w1,
                                                  const float* __restrict__ b1,
                                                  const float* __restrict__ w2,
                                                  const float* __restrict__ b2) {
    extern __shared__ char smraw[];
    float* s_w1r = (float*)smraw;
    float* s_w1i = s_w1r + 9216;
    float* s_w2r = s_w1i + 9216;
    float* s_w2i = s_w2r + 9216;
    float* s_b   = s_w2i + 9216;   // [b1r|b1i|b2r|b2i] x 96
    float* s_xr  = s_b + 384;      // [96][64]
    float* s_xi  = s_xr + 6144;

    int n  = blockIdx.y;
    int b  = blockIdx.z;
    int k0 = blockIdx.x * KT;

    const float* w1r_g = w1 + n * 9216;
    const float* w1i_g = w1 + 8 * 9216 + n * 9216;
    const float* w2r_g = w2 + n * 9216;
    const float* w2i_g = w2 + 8 * 9216 + n * 9216;
    for (int i = threadIdx.x; i < 9216; i += 256) {
        s_w1r[i] = w1r_g[i];
        s_w1i[i] = w1i_g[i];
        s_w2r[i] = w2r_g[i];
        s_w2i[i] = w2i_g[i];
    }
    if (threadIdx.x < 96) {
        int t = threadIdx.x;
        s_b[t]       = b1[n * 96 + t];
        s_b[96 + t]  = b1[768 + n * 96 + t];
        s_b[192 + t] = b2[n * 96 + t];
        s_b[288 + t] = b2[768 + n * 96 + t];
    }
    size_t base = ((size_t)b * CH + n * 96) * MODES + k0;
    for (int i = threadIdx.x; i < 6144; i += 256) {
        int d = i >> 6, mm = i & 63;
        bool ok = (k0 + mm) < MODES;
        s_xr[i] = ok ? g_Xre[base + (size_t)d * MODES + mm] : 0.0f;
        s_xi[i] = ok ? g_Xim[base + (size_t)d * MODES + mm] : 0.0f;
    }
    __syncthreads();

    int m  = threadIdx.x & 63;
    int kb = (threadIdx.x >> 6) * 24;

    float o1r[24], o1i[24];
    #pragma unroll
    for (int k = 0; k < 24; k++) { o1r[k] = s_b[kb + k]; o1i[k] = s_b[96 + kb + k]; }
    for (int d = 0; d < 96; d++) {
        float ar = s_xr[d * 64 + m];
        float ai = s_xi[d * 64 + m];
        const float* wr = s_w1r + d * 96 + kb;
        const float* wi = s_w1i + d * 96 + kb;
        #pragma unroll
        for (int k = 0; k < 24; k++) {
            o1r[k] = fmaf(ar, wr[k], fmaf(-ai, wi[k], o1r[k]));
            o1i[k] = fmaf(ai, wr[k], fmaf( ar, wi[k], o1i[k]));
        }
    }
    #pragma unroll
    for (int k = 0; k < 24; k++) { o1r[k] = fmaxf(o1r[k], 0.0f); o1i[k] = fmaxf(o1i[k], 0.0f); }
    __syncthreads();
    #pragma unroll
    for (int k = 0; k < 24; k++) { s_xr[(kb + k) * 64 + m] = o1r[k]; s_xi[(kb + k) * 64 + m] = o1i[k]; }
    __syncthreads();

    float o2r[24], o2i[24];
    #pragma unroll
    for (int k = 0; k < 24; k++) { o2r[k] = s_b[192 + kb + k]; o2i[k] = s_b[288 + kb + k]; }
    for (int d = 0; d < 96; d++) {
        float ar = s_xr[d * 64 + m];
        float ai = s_xi[d * 64 + m];
        const float* wr = s_w2r + d * 96 + kb;
        const float* wi = s_w2i + d * 96 + kb;
        #pragma unroll
        for (int k = 0; k < 24; k++) {
            o2r[k] = fmaf(ar, wr[k], fmaf(-ai, wi[k], o2r[k]));
            o2i[k] = fmaf(ai, wr[k], fmaf( ar, wi[k], o2i[k]));
        }
    }
    if (k0 + m < MODES) {
        size_t ob = ((size_t)b * CH + n * 96) * MODES + k0 + m;
        #pragma unroll
        for (int k = 0; k < 24; k++) {
            float vr = o2r[k];
            float vi = o2i[k];
            vr = copysignf(fmaxf(fabsf(vr) - LAM, 0.0f), vr);
            vi = copysignf(fmaxf(fabsf(vi) - LAM, 0.0f), vi);
            g_Xre[ob + (size_t)(kb + k) * MODES] = vr;
            g_Xim[ob + (size_t)(kb + k) * MODES] = vi;
        }
    }
}

// ---------------- inverse rfft: X planar -> yT[b*CH+c][s] ----------------
__global__ void __launch_bounds__(256) inv_fft_kernel() {
    extern __shared__ char smraw[];
    float2* A = (float2*)smraw;
    float2* B = A + 4096;
    int row = blockIdx.x;
    const float* Xre = g_Xre + (size_t)row * MODES;
    const float* Xim = g_Xim + (size_t)row * MODES;
    for (int k = threadIdx.x; k < 4096; k += 256) {
        float xkr = Xre[k],        xki = Xim[k];
        float xcr = Xre[4096 - k], xci = Xim[4096 - k];
        if (k == 0) { xki = 0.0f; xci = 0.0f; }  // irfft ignores imag at DC/Nyquist
        float Ex = 0.5f * (xkr + xcr), Ey = 0.5f * (xki - xci);
        float Gx = 0.5f * (xkr - xcr), Gy = 0.5f * (xki + xci);
        float2 w = g_wr[k];  // e^{+2pi i k/8192}
        float WOx = w.x * Gx - w.y * Gy;
        float WOy = w.x * Gy + w.y * Gx;
        float Zx = Ex - WOy;
        float Zy = Ey + WOx;
        A[k] = make_float2(INV_SCALE * Zx, -INV_SCALE * Zy);  // conj, scale folded
    }
    __syncthreads();
    float2* R = fft4096(A, B);
    float2* out = (float2*)(g_yT + (size_t)row * SEQ);
    for (int j = threadIdx.x; j < 4096; j += 256) {
        float2 r = R[j];
        out[j] = make_float2(r.x, -r.y);  // conj back -> (y[2j], y[2j+1])
    }
}

// ---------------- transpose + bias: out[b,s,c] = x[b,s,c] + yT[b,c,s] ----------------
__global__ void __launch_bounds__(256) final_kernel(const float* __restrict__ x,
                                                    float* __restrict__ out) {
    __shared__ float t[32][33];
    int b  = blockIdx.z;
    int c0 = blockIdx.x * 32;
    int s0 = blockIdx.y * 32;
    int tx = threadIdx.x, ty = threadIdx.y;
    #pragma unroll
    for (int i = 0; i < 4; i++) {
        int cc = c0 + ty + 8 * i;
        t[ty + 8 * i][tx] = g_yT[((size_t)b * CH + cc) * SEQ + s0 + tx];
    }
    __syncthreads();
    #pragma unroll
    for (int i = 0; i < 4; i++) {
        int s = s0 + ty + 8 * i;
        size_t off = ((size_t)b * SEQ + s) * CH + c0 + tx;
        out[off] = x[off] + t[tx][ty + 8 * i];
    }
}

// ---------------- launcher ----------------
extern "C" void kernel_launch(void* const* d_in, const int* in_sizes, int n_in,
                              void* d_out, int out_size) {
    const float* x  = (const float*)d_in[0];
    const float* w1 = (const float*)d_in[1];
    const float* b1 = (const float*)d_in[2];
    const float* w2 = (const float*)d_in[3];
    const float* b2 = (const float*)d_in[4];
    float* out = (float*)d_out;

    cudaFuncSetAttribute(fwd_fft_kernel, cudaFuncAttributeMaxDynamicSharedMemorySize, 65536);
    cudaFuncSetAttribute(inv_fft_kernel, cudaFuncAttributeMaxDynamicSharedMemorySize, 65536);
    cudaFuncSetAttribute(mlp_kernel,     cudaFuncAttributeMaxDynamicSharedMemorySize, MLP_SMEM);

    init_tables_kernel<<<17, 256>>>();
    fwd_fft_kernel<<<BATCH * CH, 256, 65536>>>(x);
    mlp_kernel<<<dim3((MODES + KT - 1) / KT, NBLK, BATCH), 256, MLP_SMEM>>>(w1, b1, w2, b2);
    inv_fft_kernel<<<BATCH * CH, 256, 65536>>>();
    final_kernel<<<dim3(CH / 32, SEQ / 32, BATCH), dim3(32, 8)>>>(x, out);
}

// round 3
// speedup vs baseline: 1.0879x; 1.0879x over previous
#include <cuda_runtime.h>
#include <math.h>
#include <stdint.h>

#define BATCH 4
#define SEQ   8192
#define CH    768
#define N2    4096
#define MODES 4097
#define NBLK  8
#define BLK   96
#define LAM   0.01f

#define FWD_SCALE 0.011048543456039806f   // 1/sqrt(8192)
#define INV_SCALE 0.022097086912079613f   // sqrt(8192)/4096

// ---------------- device scratch ----------------
__device__ float  g_Xre[BATCH * CH * MODES];
__device__ float  g_Xim[BATCH * CH * MODES];
__device__ float  g_yT [BATCH * CH * SEQ];
__device__ float2 g_wfft[N2];     // exp(-2*pi*i*t/4096)
__device__ float2 g_wr  [MODES];  // (cos,sin)(2*pi*k/8192)

// ---------------- tables ----------------
__global__ void init_tables_kernel() {
    int i = blockIdx.x * blockDim.x + threadIdx.x;
    if (i < N2) {
        float s, c;
        sincospif((float)i * (1.0f / 2048.0f), &s, &c);
        g_wfft[i] = make_float2(c, -s);
    }
    if (i < MODES) {
        float s, c;
        sincospif((float)i * (1.0f / 4096.0f), &s, &c);
        g_wr[i] = make_float2(c, s);
    }
}

// ---------------- complex helpers ----------------
__device__ __forceinline__ float2 cadd(float2 a, float2 b) { return make_float2(a.x + b.x, a.y + b.y); }
__device__ __forceinline__ float2 csub(float2 a, float2 b) { return make_float2(a.x - b.x, a.y - b.y); }
__device__ __forceinline__ float2 cmul(float2 a, float2 b) {
    return make_float2(fmaf(a.x, b.x, -a.y * b.y), fmaf(a.x, b.y, a.y * b.x));
}

// ---------------- packed f32x2 helpers ----------------
__device__ __forceinline__ uint64_t pk2(float lo, float hi) {
    uint64_t r;
    asm("mov.b64 %0, {%1, %2};" : "=l"(r) : "r"(__float_as_uint(lo)), "r"(__float_as_uint(hi)));
    return r;
}
__device__ __forceinline__ float2 upk2(uint64_t v) {
    uint32_t lo, hi;
    asm("mov.b64 {%0, %1}, %2;" : "=r"(lo), "=r"(hi) : "l"(v));
    return make_float2(__uint_as_float(lo), __uint_as_float(hi));
}
__device__ __forceinline__ void fma2(uint64_t& d, uint64_t a, uint64_t b) {
    asm("fma.rn.f32x2 %0, %1, %2, %3;" : "=l"(d) : "l"(a), "l"(b), "l"(d));
}

// ---------------- 4096-pt radix-4 Stockham (forward, e^{-i}) ----------------
__device__ float2* fft4096(float2* A, float2* B) {
    float2* src = A;
    float2* dst = B;
    int ls = 0;
    #pragma unroll
    for (int stage = 0; stage < 6; stage++) {
        int m = 1024 >> (2 * stage);
        for (int idx = threadIdx.x; idx < 1024; idx += 256) {
            int q = idx & ((1 << ls) - 1);
            int p = idx >> ls;
            float2 a = src[q + ((p        ) << ls)];
            float2 b = src[q + ((p +     m) << ls)];
            float2 c = src[q + ((p + 2 * m) << ls)];
            float2 d = src[q + ((p + 3 * m) << ls)];
            float2 apc = cadd(a, c), amc = csub(a, c);
            float2 bpd = cadd(b, d), bmd = csub(b, d);
            int tw = p << ls;
            float2 w1 = g_wfft[tw];
            float2 w2 = g_wfft[2 * tw];
            float2 w3 = g_wfft[3 * tw];
            float2 t1 = make_float2(amc.x + bmd.y, amc.y - bmd.x);
            float2 t3 = make_float2(amc.x - bmd.y, amc.y + bmd.x);
            dst[q + ((4 * p + 0) << ls)] = cadd(apc, bpd);
            dst[q + ((4 * p + 1) << ls)] = cmul(w1, t1);
            dst[q + ((4 * p + 2) << ls)] = cmul(w2, csub(apc, bpd));
            dst[q + ((4 * p + 3) << ls)] = cmul(w3, t3);
        }
        __syncthreads();
        float2* t = src; src = dst; dst = t;
        ls += 2;
    }
    return src;
}

// ---------------- forward rfft: x[b,s,c] -> X planar [b*CH+c][k] ----------------
__global__ void __launch_bounds__(256) fwd_fft_kernel(const float* __restrict__ x) {
    extern __shared__ char smraw[];
    float2* A = (float2*)smraw;
    float2* B = A + 4096;
    int row = blockIdx.x;
    int b = row / CH, c = row % CH;
    const float* xr = x + ((size_t)b * SEQ) * CH + c;
    for (int j = threadIdx.x; j < 4096; j += 256) {
        A[j] = make_float2(xr[(size_t)(2 * j) * CH], xr[(size_t)(2 * j + 1) * CH]);
    }
    __syncthreads();
    float2* R = fft4096(A, B);
    float* Xre = g_Xre + (size_t)row * MODES;
    float* Xim = g_Xim + (size_t)row * MODES;
    for (int k = threadIdx.x; k <= 4096; k += 256) {
        float2 Zk = R[k & 4095];
        float2 Zc = R[(4096 - k) & 4095];
        float Ex = 0.5f * (Zk.x + Zc.x), Ey = 0.5f * (Zk.y - Zc.y);
        float Ox = 0.5f * (Zk.x - Zc.x), Oy = 0.5f * (Zk.y + Zc.y);
        float2 w = g_wr[k];
        float re = Ex + w.x * Oy - w.y * Ox;
        float im = Ey - w.x * Ox - w.y * Oy;
        Xre[k] = FWD_SCALE * re;
        Xim[k] = FWD_SCALE * im;
    }
}

// ---------------- block-diagonal complex 2-layer MLP on modes (f32x2) ----------
#define KT 64
#define MLP_SMEM ((4 * 9216 + 384 + 2 * 6144) * 4)

__global__ void __launch_bounds__(256) mlp_kernel(const float* __restrict__ w1,
                                                  const float* __restrict__ b1,
                                                  const float* __restrict__ w2,
                                                  const float* __restrict__ b2) {
    extern __shared__ char smraw[];
    float* s_w1r = (float*)smraw;
    float* s_w1i = s_w1r + 9216;
    float* s_w2r = s_w1i + 9216;
    float* s_w2i = s_w2r + 9216;
    float* s_b   = s_w2i + 9216;   // [b1r|b1i|b2r|b2i] x 96
    float* s_xr  = s_b + 384;      // [96][64]
    float* s_xi  = s_xr + 6144;

    int n  = blockIdx.y;
    int b  = blockIdx.z;
    int k0 = blockIdx.x * KT;

    const float* w1r_g = w1 + n * 9216;
    const float* w1i_g = w1 + 8 * 9216 + n * 9216;
    const float* w2r_g = w2 + n * 9216;
    const float* w2i_g = w2 + 8 * 9216 + n * 9216;
    for (int i = threadIdx.x; i < 9216; i += 256) {
        s_w1r[i] = w1r_g[i];
        s_w1i[i] = w1i_g[i];
        s_w2r[i] = w2r_g[i];
        s_w2i[i] = w2i_g[i];
    }
    if (threadIdx.x < 96) {
        int t = threadIdx.x;
        s_b[t]       = b1[n * 96 + t];
        s_b[96 + t]  = b1[768 + n * 96 + t];
        s_b[192 + t] = b2[n * 96 + t];
        s_b[288 + t] = b2[768 + n * 96 + t];
    }
    size_t base = ((size_t)b * CH + n * 96) * MODES + k0;
    for (int i = threadIdx.x; i < 6144; i += 256) {
        int d = i >> 6, mm = i & 63;
        bool ok = (k0 + mm) < MODES;
        s_xr[i] = ok ? g_Xre[base + (size_t)d * MODES + mm] : 0.0f;
        s_xi[i] = ok ? g_Xim[base + (size_t)d * MODES + mm] : 0.0f;
    }
    __syncthreads();

    int m  = threadIdx.x & 63;
    int kb = (threadIdx.x >> 6) * 24;   // 24 outputs per thread = 12 f32x2 pairs

    uint64_t accr[12], acci[12];

    // ---- layer 1 ----
    #pragma unroll
    for (int p = 0; p < 12; p++) {
        accr[p] = pk2(s_b[kb + 2 * p],      s_b[kb + 2 * p + 1]);
        acci[p] = pk2(s_b[96 + kb + 2 * p], s_b[96 + kb + 2 * p + 1]);
    }
    for (int d = 0; d < 96; d++) {
        float ar = s_xr[d * 64 + m];
        float ai = s_xi[d * 64 + m];
        uint64_t arr = pk2(ar, ar);
        uint64_t aii = pk2(ai, ai);
        uint64_t nai = pk2(-ai, -ai);
        const uint64_t* wr = (const uint64_t*)(s_w1r + d * 96 + kb);
        const uint64_t* wi = (const uint64_t*)(s_w1i + d * 96 + kb);
        #pragma unroll
        for (int p = 0; p < 12; p++) {
            uint64_t wrp = wr[p];
            uint64_t wip = wi[p];
            fma2(accr[p], arr, wrp);
            fma2(acci[p], aii, wrp);
            fma2(accr[p], nai, wip);
            fma2(acci[p], arr, wip);
        }
    }
    __syncthreads();
    #pragma unroll
    for (int p = 0; p < 12; p++) {
        float2 vr = upk2(accr[p]);
        float2 vi = upk2(acci[p]);
        s_xr[(kb + 2 * p) * 64 + m]     = fmaxf(vr.x, 0.0f);
        s_xr[(kb + 2 * p + 1) * 64 + m] = fmaxf(vr.y, 0.0f);
        s_xi[(kb + 2 * p) * 64 + m]     = fmaxf(vi.x, 0.0f);
        s_xi[(kb + 2 * p + 1) * 64 + m] = fmaxf(vi.y, 0.0f);
    }
    __syncthreads();

    // ---- layer 2 ----
    #pragma unroll
    for (int p = 0; p < 12; p++) {
        accr[p] = pk2(s_b[192 + kb + 2 * p], s_b[192 + kb + 2 * p + 1]);
        acci[p] = pk2(s_b[288 + kb + 2 * p], s_b[288 + kb + 2 * p + 1]);
    }
    for (int d = 0; d < 96; d++) {
        float ar = s_xr[d * 64 + m];
        float ai = s_xi[d * 64 + m];
        uint64_t arr = pk2(ar, ar);
        uint64_t aii = pk2(ai, ai);
        uint64_t nai = pk2(-ai, -ai);
        const uint64_t* wr = (const uint64_t*)(s_w2r + d * 96 + kb);
        const uint64_t* wi = (const uint64_t*)(s_w2i + d * 96 + kb);
        #pragma unroll
        for (int p = 0; p < 12; p++) {
            uint64_t wrp = wr[p];
            uint64_t wip = wi[p];
            fma2(accr[p], arr, wrp);
            fma2(acci[p], aii, wrp);
            fma2(accr[p], nai, wip);
            fma2(acci[p], arr, wip);
        }
    }

    if (k0 + m < MODES) {
        size_t ob = ((size_t)b * CH + n * 96) * MODES + k0 + m;
        #pragma unroll
        for (int p = 0; p < 12; p++) {
            float2 vr = upk2(accr[p]);
            float2 vi = upk2(acci[p]);
            float v;
            v = vr.x; g_Xre[ob + (size_t)(kb + 2 * p) * MODES]     = copysignf(fmaxf(fabsf(v) - LAM, 0.0f), v);
            v = vr.y; g_Xre[ob + (size_t)(kb + 2 * p + 1) * MODES] = copysignf(fmaxf(fabsf(v) - LAM, 0.0f), v);
            v = vi.x; g_Xim[ob + (size_t)(kb + 2 * p) * MODES]     = copysignf(fmaxf(fabsf(v) - LAM, 0.0f), v);
            v = vi.y; g_Xim[ob + (size_t)(kb + 2 * p + 1) * MODES] = copysignf(fmaxf(fabsf(v) - LAM, 0.0f), v);
        }
    }
}

// ---------------- inverse rfft: X planar -> yT[b*CH+c][s] ----------------
__global__ void __launch_bounds__(256) inv_fft_kernel() {
    extern __shared__ char smraw[];
    float2* A = (float2*)smraw;
    float2* B = A + 4096;
    int row = blockIdx.x;
    const float* Xre = g_Xre + (size_t)row * MODES;
    const float* Xim = g_Xim + (size_t)row * MODES;
    for (int k = threadIdx.x; k < 4096; k += 256) {
        float xkr = Xre[k],        xki = Xim[k];
        float xcr = Xre[4096 - k], xci = Xim[4096 - k];
        if (k == 0) { xki = 0.0f; xci = 0.0f; }
        float Ex = 0.5f * (xkr + xcr), Ey = 0.5f * (xki - xci);
        float Gx = 0.5f * (xkr - xcr), Gy = 0.5f * (xki + xci);
        float2 w = g_wr[k];
        float WOx = w.x * Gx - w.y * Gy;
        float WOy = w.x * Gy + w.y * Gx;
        float Zx = Ex - WOy;
        float Zy = Ey + WOx;
        A[k] = make_float2(INV_SCALE * Zx, -INV_SCALE * Zy);
    }
    __syncthreads();
    float2* R = fft4096(A, B);
    float2* out = (float2*)(g_yT + (size_t)row * SEQ);
    for (int j = threadIdx.x; j < 4096; j += 256) {
        float2 r = R[j];
        out[j] = make_float2(r.x, -r.y);
    }
}

// ---------------- transpose + bias: out[b,s,c] = x[b,s,c] + yT[b,c,s] --------
__global__ void __launch_bounds__(256) final_kernel(const float* __restrict__ x,
                                                    float* __restrict__ out) {
    __shared__ float t[32][33];
    int b  = blockIdx.z;
    int c0 = blockIdx.x * 32;
    int s0 = blockIdx.y * 32;
    int tx = threadIdx.x, ty = threadIdx.y;
    #pragma unroll
    for (int i = 0; i < 4; i++) {
        int cc = c0 + ty + 8 * i;
        t[ty + 8 * i][tx] = g_yT[((size_t)b * CH + cc) * SEQ + s0 + tx];
    }
    __syncthreads();
    #pragma unroll
    for (int i = 0; i < 4; i++) {
        int s = s0 + ty + 8 * i;
        size_t off = ((size_t)b * SEQ + s) * CH + c0 + tx;
        out[off] = x[off] + t[tx][ty + 8 * i];
    }
}

// ---------------- launcher ----------------
extern "C" void kernel_launch(void* const* d_in, const int* in_sizes, int n_in,
                              void* d_out, int out_size) {
    const float* x  = (const float*)d_in[0];
    const float* w1 = (const float*)d_in[1];
    const float* b1 = (const float*)d_in[2];
    const float* w2 = (const float*)d_in[3];
    const float* b2 = (const float*)d_in[4];
    float* out = (float*)d_out;

    cudaFuncSetAttribute(fwd_fft_kernel, cudaFuncAttributeMaxDynamicSharedMemorySize, 65536);
    cudaFuncSetAttribute(inv_fft_kernel, cudaFuncAttributeMaxDynamicSharedMemorySize, 65536);
    cudaFuncSetAttribute(mlp_kernel,     cudaFuncAttributeMaxDynamicSharedMemorySize, MLP_SMEM);

    init_tables_kernel<<<17, 256>>>();
    fwd_fft_kernel<<<BATCH * CH, 256, 65536>>>(x);
    mlp_kernel<<<dim3((MODES + KT - 1) / KT, NBLK, BATCH), 256, MLP_SMEM>>>(w1, b1, w2, b2);
    inv_fft_kernel<<<BATCH * CH, 256, 65536>>>();
    final_kernel<<<dim3(CH / 32, SEQ / 32, BATCH), dim3(32, 8)>>>(x, out);
}

// round 4
// speedup vs baseline: 1.6863x; 1.5501x over previous
#include <cuda_runtime.h>
#include <cuda_bf16.h>
#include <math.h>
#include <stdint.h>

#define BATCH 4
#define SEQ   8192
#define CH    768
#define N2    4096
#define MODES 4097
#define NBLK  8
#define BLK   96
#define LAM   0.01f

#define FWD_SCALE 0.011048543456039806f   // 1/sqrt(8192)
#define INV_SCALE 0.022097086912079613f   // sqrt(8192)/4096

// ---------------- device scratch ----------------
__device__ float  g_Xre[BATCH * CH * MODES];
__device__ float  g_Xim[BATCH * CH * MODES];
__device__ float  g_yT [BATCH * CH * SEQ];
__device__ float2 g_wfft[N2];     // exp(-2*pi*i*t/4096)
__device__ float2 g_wr  [MODES];  // (cos,sin)(2*pi*k/8192)

// ---------------- tables ----------------
__global__ void init_tables_kernel() {
    int i = blockIdx.x * blockDim.x + threadIdx.x;
    if (i < N2) {
        float s, c;
        sincospif((float)i * (1.0f / 2048.0f), &s, &c);
        g_wfft[i] = make_float2(c, -s);
    }
    if (i < MODES) {
        float s, c;
        sincospif((float)i * (1.0f / 4096.0f), &s, &c);
        g_wr[i] = make_float2(c, s);
    }
}

// ---------------- complex helpers ----------------
__device__ __forceinline__ float2 cadd(float2 a, float2 b) { return make_float2(a.x + b.x, a.y + b.y); }
__device__ __forceinline__ float2 csub(float2 a, float2 b) { return make_float2(a.x - b.x, a.y - b.y); }
__device__ __forceinline__ float2 cmul(float2 a, float2 b) {
    return make_float2(fmaf(a.x, b.x, -a.y * b.y), fmaf(a.x, b.y, a.y * b.x));
}

// ---------------- 4096-pt radix-4 Stockham (forward, e^{-i}) ----------------
__device__ float2* fft4096(float2* A, float2* B) {
    float2* src = A;
    float2* dst = B;
    int ls = 0;
    #pragma unroll
    for (int stage = 0; stage < 6; stage++) {
        int m = 1024 >> (2 * stage);
        for (int idx = threadIdx.x; idx < 1024; idx += 256) {
            int q = idx & ((1 << ls) - 1);
            int p = idx >> ls;
            float2 a = src[q + ((p        ) << ls)];
            float2 b = src[q + ((p +     m) << ls)];
            float2 c = src[q + ((p + 2 * m) << ls)];
            float2 d = src[q + ((p + 3 * m) << ls)];
            float2 apc = cadd(a, c), amc = csub(a, c);
            float2 bpd = cadd(b, d), bmd = csub(b, d);
            int tw = p << ls;
            float2 w1 = g_wfft[tw];
            float2 w2 = g_wfft[2 * tw];
            float2 w3 = g_wfft[3 * tw];
            float2 t1 = make_float2(amc.x + bmd.y, amc.y - bmd.x);
            float2 t3 = make_float2(amc.x - bmd.y, amc.y + bmd.x);
            dst[q + ((4 * p + 0) << ls)] = cadd(apc, bpd);
            dst[q + ((4 * p + 1) << ls)] = cmul(w1, t1);
            dst[q + ((4 * p + 2) << ls)] = cmul(w2, csub(apc, bpd));
            dst[q + ((4 * p + 3) << ls)] = cmul(w3, t3);
        }
        __syncthreads();
        float2* t = src; src = dst; dst = t;
        ls += 2;
    }
    return src;
}

// ---------------- forward rfft: x[b,s,c] -> X planar [b*CH+c][k] ----------------
__global__ void __launch_bounds__(256) fwd_fft_kernel(const float* __restrict__ x) {
    extern __shared__ char smraw[];
    float2* A = (float2*)smraw;
    float2* B = A + 4096;
    int row = blockIdx.x;
    int b = row / CH, c = row % CH;
    const float* xr = x + ((size_t)b * SEQ) * CH + c;
    for (int j = threadIdx.x; j < 4096; j += 256) {
        A[j] = make_float2(xr[(size_t)(2 * j) * CH], xr[(size_t)(2 * j + 1) * CH]);
    }
    __syncthreads();
    float2* R = fft4096(A, B);
    float* Xre = g_Xre + (size_t)row * MODES;
    float* Xim = g_Xim + (size_t)row * MODES;
    for (int k = threadIdx.x; k <= 4096; k += 256) {
        float2 Zk = R[k & 4095];
        float2 Zc = R[(4096 - k) & 4095];
        float Ex = 0.5f * (Zk.x + Zc.x), Ey = 0.5f * (Zk.y - Zc.y);
        float Ox = 0.5f * (Zk.x - Zc.x), Oy = 0.5f * (Zk.y + Zc.y);
        float2 w = g_wr[k];
        float re = Ex + w.x * Oy - w.y * Ox;
        float im = Ey - w.x * Ox - w.y * Oy;
        Xre[k] = FWD_SCALE * re;
        Xim[k] = FWD_SCALE * im;
    }
}

// ============== tensor-core block-diagonal complex 2-layer MLP ==============
// CTA = (mode-tile of 128, block n, batch b). 8 warps x 16 modes.
// Weights transposed [n_out][d] bf16 in smem, row stride 98 (conflict-free).
// Complex mults via pre-negated wi copies: o_r += xr*wr + xi*(-wi); o_i += xi*wr + xr*wi.

#define MT    128          // modes per CTA
#define XPAD  98           // bf16 row stride (49 words; 17g mod 32 -> conflict-free)
#define SW_OFF   0                           // 6 * 96 * 98 bf16
#define SXR_OFF  (6 * 96 * XPAD * 2)         // 112896
#define SXI_OFF  (SXR_OFF + MT * XPAD * 2)   // +25088
#define SB_OFF   (SXI_OFF + MT * XPAD * 2)   // +25088
#define MLP_SMEM (SB_OFF + 4 * 96 * 4)       // +1536 = 164608

__device__ __forceinline__ void mma_bf16(float* c, const uint32_t* a, uint32_t b0, uint32_t b1) {
    asm volatile(
        "mma.sync.aligned.m16n8k16.row.col.f32.bf16.bf16.f32 "
        "{%0,%1,%2,%3}, {%4,%5,%6,%7}, {%8,%9}, {%0,%1,%2,%3};"
        : "+f"(c[0]), "+f"(c[1]), "+f"(c[2]), "+f"(c[3])
        : "r"(a[0]), "r"(a[1]), "r"(a[2]), "r"(a[3]), "r"(b0), "r"(b1));
}

__global__ void __launch_bounds__(256) mlp_mma_kernel(const float* __restrict__ w1,
                                                      const float* __restrict__ b1,
                                                      const float* __restrict__ w2,
                                                      const float* __restrict__ b2) {
    extern __shared__ char sm[];
    __nv_bfloat16* s_w  = (__nv_bfloat16*)(sm + SW_OFF);   // [6][96][XPAD]: w1r,w1i,-w1i,w2r,w2i,-w2i
    __nv_bfloat16* s_xr = (__nv_bfloat16*)(sm + SXR_OFF);  // [MT][XPAD]
    __nv_bfloat16* s_xi = (__nv_bfloat16*)(sm + SXI_OFF);
    float*         s_bv = (float*)(sm + SB_OFF);           // [4][96]: b1r,b1i,b2r,b2i

    const int tid = threadIdx.x;
    const int n   = blockIdx.y;
    const int b   = blockIdx.z;
    const int m0  = blockIdx.x * MT;

    // ---- load weights (transposed, bf16, with negated-wi copies) ----
    const float* g_w1r = w1 + n * 9216;
    const float* g_w1i = w1 + 73728 + n * 9216;
    const float* g_w2r = w2 + n * 9216;
    const float* g_w2i = w2 + 73728 + n * 9216;
    for (int i = tid; i < 9216; i += 256) {
        int d = i / 96, k = i % 96;          // gmem [d][k], coalesced in k
        int o = k * XPAD + d;                // smem [k][d]
        float v;
        v = g_w1r[i]; s_w[0 * 96 * XPAD + o] = __float2bfloat16_rn(v);
        v = g_w1i[i]; s_w[1 * 96 * XPAD + o] = __float2bfloat16_rn(v);
                      s_w[2 * 96 * XPAD + o] = __float2bfloat16_rn(-v);
        v = g_w2r[i]; s_w[3 * 96 * XPAD + o] = __float2bfloat16_rn(v);
        v = g_w2i[i]; s_w[4 * 96 * XPAD + o] = __float2bfloat16_rn(v);
                      s_w[5 * 96 * XPAD + o] = __float2bfloat16_rn(-v);
    }
    if (tid < 96) {
        s_bv[tid]       = b1[n * 96 + tid];
        s_bv[96 + tid]  = b1[768 + n * 96 + tid];
        s_bv[192 + tid] = b2[n * 96 + tid];
        s_bv[288 + tid] = b2[768 + n * 96 + tid];
    }

    // ---- load x tile [mode][d] bf16 (transpose from planar [d][mode]) ----
    size_t rowbase = ((size_t)b * CH + n * 96) * (size_t)MODES;
    for (int i = tid; i < 96 * MT; i += 256) {
        int d = i >> 7, mm = i & (MT - 1);
        int mode = m0 + mm;
        bool ok = mode < MODES;
        float vr = ok ? g_Xre[rowbase + (size_t)d * MODES + mode] : 0.0f;
        float vi = ok ? g_Xim[rowbase + (size_t)d * MODES + mode] : 0.0f;
        s_xr[mm * XPAD + d] = __float2bfloat16_rn(vr);
        s_xi[mm * XPAD + d] = __float2bfloat16_rn(vi);
    }
    __syncthreads();

    const int lane = tid & 31;
    const int warp = tid >> 5;
    const int g  = lane >> 2;       // 0..7
    const int t  = lane & 3;        // 0..3
    const int mrow = warp * 16;     // this warp's 16 modes

    const uint32_t* Ww = (const uint32_t*)s_w;
    const uint32_t* Xr = (const uint32_t*)s_xr;
    const uint32_t* Xi = (const uint32_t*)s_xi;
    const int RS = XPAD / 2;        // 49 words per row

    float cr[12][4], ci[12][4];

    // ================= layer 1 =================
    #pragma unroll
    for (int nt = 0; nt < 12; nt++) {
        float br0 = s_bv[nt * 8 + 2 * t], br1 = s_bv[nt * 8 + 2 * t + 1];
        float bi0 = s_bv[96 + nt * 8 + 2 * t], bi1 = s_bv[96 + nt * 8 + 2 * t + 1];
        cr[nt][0] = br0; cr[nt][1] = br1; cr[nt][2] = br0; cr[nt][3] = br1;
        ci[nt][0] = bi0; ci[nt][1] = bi1; ci[nt][2] = bi0; ci[nt][3] = bi1;
    }
    #pragma unroll
    for (int k = 0; k < 6; k++) {
        int kw = k * 8 + t;  // word offset of cols 2t,2t+1 within k-tile
        uint32_t ar[4], ai[4];
        ar[0] = Xr[(mrow + g) * RS + kw];     ar[1] = Xr[(mrow + g + 8) * RS + kw];
        ar[2] = Xr[(mrow + g) * RS + kw + 4]; ar[3] = Xr[(mrow + g + 8) * RS + kw + 4];
        ai[0] = Xi[(mrow + g) * RS + kw];     ai[1] = Xi[(mrow + g + 8) * RS + kw];
        ai[2] = Xi[(mrow + g) * RS + kw + 4]; ai[3] = Xi[(mrow + g + 8) * RS + kw + 4];
        #pragma unroll
        for (int nt = 0; nt < 12; nt++) {
            int wrow = (nt * 8 + g) * RS + kw;
            uint32_t wr0  = Ww[0 * 96 * RS + wrow], wr1  = Ww[0 * 96 * RS + wrow + 4];
            uint32_t wi0  = Ww[1 * 96 * RS + wrow], wi1  = Ww[1 * 96 * RS + wrow + 4];
            uint32_t nwi0 = Ww[2 * 96 * RS + wrow], nwi1 = Ww[2 * 96 * RS + wrow + 4];
            mma_bf16(cr[nt], ar, wr0, wr1);
            mma_bf16(cr[nt], ai, nwi0, nwi1);
            mma_bf16(ci[nt], ai, wr0, wr1);
            mma_bf16(ci[nt], ar, wi0, wi1);
        }
    }
    __syncwarp();
    // relu -> bf16 -> back into x tile (warp-private rows)
    {
        uint32_t* Xrw = (uint32_t*)s_xr;
        uint32_t* Xiw = (uint32_t*)s_xi;
        #pragma unroll
        for (int nt = 0; nt < 12; nt++) {
            int cw = nt * 4 + t;  // word offset of cols (nt*8+2t)/2
            __nv_bfloat162 h;
            h = __floats2bfloat162_rn(fmaxf(cr[nt][0], 0.0f), fmaxf(cr[nt][1], 0.0f));
            Xrw[(mrow + g) * RS + cw] = *(uint32_t*)&h;
            h = __floats2bfloat162_rn(fmaxf(cr[nt][2], 0.0f), fmaxf(cr[nt][3], 0.0f));
            Xrw[(mrow + g + 8) * RS + cw] = *(uint32_t*)&h;
            h = __floats2bfloat162_rn(fmaxf(ci[nt][0], 0.0f), fmaxf(ci[nt][1], 0.0f));
            Xiw[(mrow + g) * RS + cw] = *(uint32_t*)&h;
            h = __floats2bfloat162_rn(fmaxf(ci[nt][2], 0.0f), fmaxf(ci[nt][3], 0.0f));
            Xiw[(mrow + g + 8) * RS + cw] = *(uint32_t*)&h;
        }
    }
    __syncwarp();

    // ================= layer 2 =================
    #pragma unroll
    for (int nt = 0; nt < 12; nt++) {
        float br0 = s_bv[192 + nt * 8 + 2 * t], br1 = s_bv[192 + nt * 8 + 2 * t + 1];
        float bi0 = s_bv[288 + nt * 8 + 2 * t], bi1 = s_bv[288 + nt * 8 + 2 * t + 1];
        cr[nt][0] = br0; cr[nt][1] = br1; cr[nt][2] = br0; cr[nt][3] = br1;
        ci[nt][0] = bi0; ci[nt][1] = bi1; ci[nt][2] = bi0; ci[nt][3] = bi1;
    }
    #pragma unroll
    for (int k = 0; k < 6; k++) {
        int kw = k * 8 + t;
        uint32_t ar[4], ai[4];
        ar[0] = Xr[(mrow + g) * RS + kw];     ar[1] = Xr[(mrow + g + 8) * RS + kw];
        ar[2] = Xr[(mrow + g) * RS + kw + 4]; ar[3] = Xr[(mrow + g + 8) * RS + kw + 4];
        ai[0] = Xi[(mrow + g) * RS + kw];     ai[1] = Xi[(mrow + g + 8) * RS + kw];
        ai[2] = Xi[(mrow + g) * RS + kw + 4]; ai[3] = Xi[(mrow + g + 8) * RS + kw + 4];
        #pragma unroll
        for (int nt = 0; nt < 12; nt++) {
            int wrow = (nt * 8 + g) * RS + kw;
            uint32_t wr0  = Ww[3 * 96 * RS + wrow], wr1  = Ww[3 * 96 * RS + wrow + 4];
            uint32_t wi0  = Ww[4 * 96 * RS + wrow], wi1  = Ww[4 * 96 * RS + wrow + 4];
            uint32_t nwi0 = Ww[5 * 96 * RS + wrow], nwi1 = Ww[5 * 96 * RS + wrow + 4];
            mma_bf16(cr[nt], ar, wr0, wr1);
            mma_bf16(cr[nt], ai, nwi0, nwi1);
            mma_bf16(ci[nt], ai, wr0, wr1);
            mma_bf16(ci[nt], ar, wi0, wi1);
        }
    }

    // ---- softshrink + store back to planar spectrum ----
    int mode_lo = m0 + mrow + g;
    int mode_hi = mode_lo + 8;
    #pragma unroll
    for (int nt = 0; nt < 12; nt++) {
        #pragma unroll
        for (int j = 0; j < 4; j++) {
            int col  = nt * 8 + 2 * t + (j & 1);
            int mode = (j < 2) ? mode_lo : mode_hi;
            if (mode < MODES) {
                size_t off = rowbase + (size_t)col * MODES + mode;
                float vr = cr[nt][j];
                float vi = ci[nt][j];
                g_Xre[off] = copysignf(fmaxf(fabsf(vr) - LAM, 0.0f), vr);
                g_Xim[off] = copysignf(fmaxf(fabsf(vi) - LAM, 0.0f), vi);
            }
        }
    }
}

// ---------------- inverse rfft: X planar -> yT[b*CH+c][s] ----------------
__global__ void __launch_bounds__(256) inv_fft_kernel() {
    extern __shared__ char smraw[];
    float2* A = (float2*)smraw;
    float2* B = A + 4096;
    int row = blockIdx.x;
    const float* Xre = g_Xre + (size_t)row * MODES;
    const float* Xim = g_Xim + (size_t)row * MODES;
    for (int k = threadIdx.x; k < 4096; k += 256) {
        float xkr = Xre[k],        xki = Xim[k];
        float xcr = Xre[4096 - k], xci = Xim[4096 - k];
        if (k == 0) { xki = 0.0f; xci = 0.0f; }
        float Ex = 0.5f * (xkr + xcr), Ey = 0.5f * (xki - xci);
        float Gx = 0.5f * (xkr - xcr), Gy = 0.5f * (xki + xci);
        float2 w = g_wr[k];
        float WOx = w.x * Gx - w.y * Gy;
        float WOy = w.x * Gy + w.y * Gx;
        float Zx = Ex - WOy;
        float Zy = Ey + WOx;
        A[k] = make_float2(INV_SCALE * Zx, -INV_SCALE * Zy);
    }
    __syncthreads();
    float2* R = fft4096(A, B);
    float2* out = (float2*)(g_yT + (size_t)row * SEQ);
    for (int j = threadIdx.x; j < 4096; j += 256) {
        float2 r = R[j];
        out[j] = make_float2(r.x, -r.y);
    }
}

// ---------------- transpose + bias: out[b,s,c] = x[b,s,c] + yT[b,c,s] --------
__global__ void __launch_bounds__(256) final_kernel(const float* __restrict__ x,
                                                    float* __restrict__ out) {
    __shared__ float t[32][33];
    int b  = blockIdx.z;
    int c0 = blockIdx.x * 32;
    int s0 = blockIdx.y * 32;
    int tx = threadIdx.x, ty = threadIdx.y;
    #pragma unroll
    for (int i = 0; i < 4; i++) {
        int cc = c0 + ty + 8 * i;
        t[ty + 8 * i][tx] = g_yT[((size_t)b * CH + cc) * SEQ + s0 + tx];
    }
    __syncthreads();
    #pragma unroll
    for (int i = 0; i < 4; i++) {
        int s = s0 + ty + 8 * i;
        size_t off = ((size_t)b * SEQ + s) * CH + c0 + tx;
        out[off] = x[off] + t[tx][ty + 8 * i];
    }
}

// ---------------- launcher ----------------
extern "C" void kernel_launch(void* const* d_in, const int* in_sizes, int n_in,
                              void* d_out, int out_size) {
    const float* x  = (const float*)d_in[0];
    const float* w1 = (const float*)d_in[1];
    const float* b1 = (const float*)d_in[2];
    const float* w2 = (const float*)d_in[3];
    const float* b2 = (const float*)d_in[4];
    float* out = (float*)d_out;

    cudaFuncSetAttribute(fwd_fft_kernel, cudaFuncAttributeMaxDynamicSharedMemorySize, 65536);
    cudaFuncSetAttribute(inv_fft_kernel, cudaFuncAttributeMaxDynamicSharedMemorySize, 65536);
    cudaFuncSetAttribute(mlp_mma_kernel, cudaFuncAttributeMaxDynamicSharedMemorySize, MLP_SMEM);

    init_tables_kernel<<<17, 256>>>();
    fwd_fft_kernel<<<BATCH * CH, 256, 65536>>>(x);
    mlp_mma_kernel<<<dim3((MODES + MT - 1) / MT, NBLK, BATCH), 256, MLP_SMEM>>>(w1, b1, w2, b2);
    inv_fft_kernel<<<BATCH * CH, 256, 65536>>>();
    final_kernel<<<dim3(CH / 32, SEQ / 32, BATCH), dim3(32, 8)>>>(x, out);
}

// round 5
// speedup vs baseline: 1.7443x; 1.0344x over previous
#include <cuda_runtime.h>
#include <cuda_bf16.h>
#include <math.h>
#include <stdint.h>

#define BATCH 4
#define SEQ   8192
#define CH    768
#define N2    4096
#define MODES 4097
#define NBLK  8
#define LAM   0.01f

#define FWD_SCALE 0.011048543456039806f   // 1/sqrt(8192)
#define INV_SCALE 0.022097086912079613f   // sqrt(8192)/4096

// padded smem indexing: 1 extra float2 per 32 -> kills 128B-stride conflicts
#define IX(i) ((i) + ((i) >> 5))
#define FFT_BUF 4224                      // IX(4095)=4222 < 4224
#define FFT_SMEM (2 * FFT_BUF * 8)        // 67584 bytes

// ---------------- device scratch ----------------
__device__ float  g_Xre[BATCH * CH * MODES];
__device__ float  g_Xim[BATCH * CH * MODES];
__device__ float  g_yT [BATCH * CH * SEQ];
__device__ float2 g_wfft[N2];     // exp(-2*pi*i*t/4096)
__device__ float2 g_wr  [MODES];  // (cos,sin)(2*pi*k/8192)

// ---------------- tables ----------------
__global__ void init_tables_kernel() {
    int i = blockIdx.x * blockDim.x + threadIdx.x;
    if (i < N2) {
        float s, c;
        sincospif((float)i * (1.0f / 2048.0f), &s, &c);
        g_wfft[i] = make_float2(c, -s);
    }
    if (i < MODES) {
        float s, c;
        sincospif((float)i * (1.0f / 4096.0f), &s, &c);
        g_wr[i] = make_float2(c, s);
    }
}

// ---------------- complex helpers ----------------
__device__ __forceinline__ float2 cadd(float2 a, float2 b) { return make_float2(a.x + b.x, a.y + b.y); }
__device__ __forceinline__ float2 csub(float2 a, float2 b) { return make_float2(a.x - b.x, a.y - b.y); }
__device__ __forceinline__ float2 cmul(float2 a, float2 b) {
    return make_float2(fmaf(a.x, b.x, -a.y * b.y), fmaf(a.x, b.y, a.y * b.x));
}

// forward DFT4 (e^{-i}), in place
__device__ __forceinline__ void dft4(float2& a0, float2& a1, float2& a2, float2& a3) {
    float2 t0 = cadd(a0, a2), t1 = csub(a0, a2);
    float2 t2 = cadd(a1, a3), t3 = csub(a1, a3);
    a0 = cadd(t0, t2);
    a2 = csub(t0, t2);
    a1 = make_float2(t1.x + t3.y, t1.y - t3.x);   // t1 - i t3
    a3 = make_float2(t1.x - t3.y, t1.y + t3.x);   // t1 + i t3
}

// 16-pt DFT in registers; output X[j] lands in v[4*(j&3) + (j>>2)]
__device__ __forceinline__ void dft16(float2 v[16]) {
    #pragma unroll
    for (int i = 0; i < 4; i++) dft4(v[i], v[i + 4], v[i + 8], v[i + 12]);
    const float C1 = 0.92387953251128674f, S1 = 0.38268343236508978f, R = 0.70710678118654752f;
    v[5]  = cmul(make_float2( C1, -S1), v[5]);
    v[6]  = cmul(make_float2(  R,  -R), v[6]);
    v[7]  = cmul(make_float2( S1, -C1), v[7]);
    v[9]  = cmul(make_float2(  R,  -R), v[9]);
    v[10] = make_float2(v[10].y, -v[10].x);        // * -i
    v[11] = cmul(make_float2( -R,  -R), v[11]);
    v[13] = cmul(make_float2( S1, -C1), v[13]);
    v[14] = cmul(make_float2( -R,  -R), v[14]);
    v[15] = cmul(make_float2(-C1,  S1), v[15]);
    #pragma unroll
    for (int k1 = 0; k1 < 4; k1++) dft4(v[4 * k1], v[4 * k1 + 1], v[4 * k1 + 2], v[4 * k1 + 3]);
}

// ---------------- 4096-pt radix-16 Stockham (forward, e^{-i}), 3 stages -----
// 256 threads, one 16-pt butterfly per thread per stage. Padded (IX) addressing.
__device__ float2* fft4096_r16(float2* A, float2* B) {
    float2* src = A;
    float2* dst = B;
    int ls = 0;
    #pragma unroll
    for (int stage = 0; stage < 3; stage++) {
        int m = 256 >> (4 * stage);
        int idx = threadIdx.x;
        int q = idx & ((1 << ls) - 1);
        int p = idx >> ls;
        float2 v[16];
        #pragma unroll
        for (int j = 0; j < 16; j++)
            v[j] = src[IX(q + ((p + j * m) << ls))];
        dft16(v);
        int twb = p << ls;   // p * sstr; stage 2 has p==0 -> all twiddles = 1
        #pragma unroll
        for (int j = 0; j < 16; j++) {
            float2 y = v[4 * (j & 3) + (j >> 2)];
            float2 w = g_wfft[j * twb];
            dst[IX(q + ((16 * p + j) << ls))] = cmul(w, y);
        }
        __syncthreads();
        float2* t = src; src = dst; dst = t;
        ls += 4;
    }
    return src;
}

// ---------------- forward rfft: x[b,s,c] -> X planar [b*CH+c][k] ------------
__global__ void __launch_bounds__(256, 2) fwd_fft_kernel(const float* __restrict__ x) {
    extern __shared__ char smraw[];
    float2* A = (float2*)smraw;
    float2* B = A + FFT_BUF;
    int row = blockIdx.x;
    int b = row / CH, c = row % CH;
    const float* xr = x + ((size_t)b * SEQ) * CH + c;
    for (int j = threadIdx.x; j < 4096; j += 256) {
        A[IX(j)] = make_float2(xr[(size_t)(2 * j) * CH], xr[(size_t)(2 * j + 1) * CH]);
    }
    __syncthreads();
    float2* R = fft4096_r16(A, B);
    float* Xre = g_Xre + (size_t)row * MODES;
    float* Xim = g_Xim + (size_t)row * MODES;
    for (int k = threadIdx.x; k <= 4096; k += 256) {
        float2 Zk = R[IX(k & 4095)];
        float2 Zc = R[IX((4096 - k) & 4095)];
        float Ex = 0.5f * (Zk.x + Zc.x), Ey = 0.5f * (Zk.y - Zc.y);
        float Ox = 0.5f * (Zk.x - Zc.x), Oy = 0.5f * (Zk.y + Zc.y);
        float2 w = g_wr[k];
        float re = Ex + w.x * Oy - w.y * Ox;
        float im = Ey - w.x * Ox - w.y * Oy;
        Xre[k] = FWD_SCALE * re;
        Xim[k] = FWD_SCALE * im;
    }
}

// ============== tensor-core block-diagonal complex 2-layer MLP ==============
// CTA = (mode-tile of 256, block n, batch b). 8 warps x 32 modes (2 passes of 16).
#define MT    256
#define XPAD  98
#define SW_OFF   0                           // 6 * 96 * 98 bf16 = 112896
#define SXR_OFF  (6 * 96 * XPAD * 2)
#define SXI_OFF  (SXR_OFF + MT * XPAD * 2)   // +50176
#define SB_OFF   (SXI_OFF + MT * XPAD * 2)   // +50176
#define MLP_SMEM (SB_OFF + 4 * 96 * 4)       // +1536 = 214784

__device__ __forceinline__ void mma_bf16(float* c, const uint32_t* a, uint32_t b0, uint32_t b1) {
    asm volatile(
        "mma.sync.aligned.m16n8k16.row.col.f32.bf16.bf16.f32 "
        "{%0,%1,%2,%3}, {%4,%5,%6,%7}, {%8,%9}, {%0,%1,%2,%3};"
        : "+f"(c[0]), "+f"(c[1]), "+f"(c[2]), "+f"(c[3])
        : "r"(a[0]), "r"(a[1]), "r"(a[2]), "r"(a[3]), "r"(b0), "r"(b1));
}

__global__ void __launch_bounds__(256) mlp_mma_kernel(const float* __restrict__ w1,
                                                      const float* __restrict__ b1,
                                                      const float* __restrict__ w2,
                                                      const float* __restrict__ b2) {
    extern __shared__ char sm[];
    __nv_bfloat16* s_w  = (__nv_bfloat16*)(sm + SW_OFF);   // [6][96][XPAD]: w1r,w1i,-w1i,w2r,w2i,-w2i
    __nv_bfloat16* s_xr = (__nv_bfloat16*)(sm + SXR_OFF);  // [MT][XPAD]
    __nv_bfloat16* s_xi = (__nv_bfloat16*)(sm + SXI_OFF);
    float*         s_bv = (float*)(sm + SB_OFF);           // [4][96]

    const int tid = threadIdx.x;
    const int n   = blockIdx.y;
    const int b   = blockIdx.z;
    const int m0  = blockIdx.x * MT;

    const float* g_w1r = w1 + n * 9216;
    const float* g_w1i = w1 + 73728 + n * 9216;
    const float* g_w2r = w2 + n * 9216;
    const float* g_w2i = w2 + 73728 + n * 9216;
    for (int i = tid; i < 9216; i += 256) {
        int d = i / 96, k = i % 96;
        int o = k * XPAD + d;
        float v;
        v = g_w1r[i]; s_w[0 * 96 * XPAD + o] = __float2bfloat16_rn(v);
        v = g_w1i[i]; s_w[1 * 96 * XPAD + o] = __float2bfloat16_rn(v);
                      s_w[2 * 96 * XPAD + o] = __float2bfloat16_rn(-v);
        v = g_w2r[i]; s_w[3 * 96 * XPAD + o] = __float2bfloat16_rn(v);
        v = g_w2i[i]; s_w[4 * 96 * XPAD + o] = __float2bfloat16_rn(v);
                      s_w[5 * 96 * XPAD + o] = __float2bfloat16_rn(-v);
    }
    if (tid < 96) {
        s_bv[tid]       = b1[n * 96 + tid];
        s_bv[96 + tid]  = b1[768 + n * 96 + tid];
        s_bv[192 + tid] = b2[n * 96 + tid];
        s_bv[288 + tid] = b2[768 + n * 96 + tid];
    }

    size_t rowbase = ((size_t)b * CH + n * 96) * (size_t)MODES;
    for (int i = tid; i < 96 * MT; i += 256) {
        int d = i >> 8, mm = i & (MT - 1);
        int mode = m0 + mm;
        bool ok = mode < MODES;
        float vr = ok ? g_Xre[rowbase + (size_t)d * MODES + mode] : 0.0f;
        float vi = ok ? g_Xim[rowbase + (size_t)d * MODES + mode] : 0.0f;
        s_xr[mm * XPAD + d] = __float2bfloat16_rn(vr);
        s_xi[mm * XPAD + d] = __float2bfloat16_rn(vi);
    }
    __syncthreads();

    const int lane = tid & 31;
    const int warp = tid >> 5;
    const int g  = lane >> 2;
    const int t  = lane & 3;

    const uint32_t* Ww = (const uint32_t*)s_w;
    const uint32_t* Xr = (const uint32_t*)s_xr;
    const uint32_t* Xi = (const uint32_t*)s_xi;
    const int RS = XPAD / 2;   // 49

    for (int h = 0; h < 2; h++) {
        const int mrow = warp * 32 + h * 16;
        float cr[12][4], ci[12][4];

        // ---------- layer 1 ----------
        #pragma unroll
        for (int nt = 0; nt < 12; nt++) {
            float br0 = s_bv[nt * 8 + 2 * t], br1 = s_bv[nt * 8 + 2 * t + 1];
            float bi0 = s_bv[96 + nt * 8 + 2 * t], bi1 = s_bv[96 + nt * 8 + 2 * t + 1];
            cr[nt][0] = br0; cr[nt][1] = br1; cr[nt][2] = br0; cr[nt][3] = br1;
            ci[nt][0] = bi0; ci[nt][1] = bi1; ci[nt][2] = bi0; ci[nt][3] = bi1;
        }
        #pragma unroll
        for (int k = 0; k < 6; k++) {
            int kw = k * 8 + t;
            uint32_t ar[4], ai[4];
            ar[0] = Xr[(mrow + g) * RS + kw];     ar[1] = Xr[(mrow + g + 8) * RS + kw];
            ar[2] = Xr[(mrow + g) * RS + kw + 4]; ar[3] = Xr[(mrow + g + 8) * RS + kw + 4];
            ai[0] = Xi[(mrow + g) * RS + kw];     ai[1] = Xi[(mrow + g + 8) * RS + kw];
            ai[2] = Xi[(mrow + g) * RS + kw + 4]; ai[3] = Xi[(mrow + g + 8) * RS + kw + 4];
            #pragma unroll
            for (int nt = 0; nt < 12; nt++) {
                int wrow = (nt * 8 + g) * RS + kw;
                uint32_t wr0  = Ww[0 * 96 * RS + wrow], wr1  = Ww[0 * 96 * RS + wrow + 4];
                uint32_t wi0  = Ww[1 * 96 * RS + wrow], wi1  = Ww[1 * 96 * RS + wrow + 4];
                uint32_t nwi0 = Ww[2 * 96 * RS + wrow], nwi1 = Ww[2 * 96 * RS + wrow + 4];
                mma_bf16(cr[nt], ar, wr0, wr1);
                mma_bf16(cr[nt], ai, nwi0, nwi1);
                mma_bf16(ci[nt], ai, wr0, wr1);
                mma_bf16(ci[nt], ar, wi0, wi1);
            }
        }
        __syncwarp();
        {
            uint32_t* Xrw = (uint32_t*)s_xr;
            uint32_t* Xiw = (uint32_t*)s_xi;
            #pragma unroll
            for (int nt = 0; nt < 12; nt++) {
                int cw = nt * 4 + t;
                __nv_bfloat162 hh;
                hh = __floats2bfloat162_rn(fmaxf(cr[nt][0], 0.0f), fmaxf(cr[nt][1], 0.0f));
                Xrw[(mrow + g) * RS + cw] = *(uint32_t*)&hh;
                hh = __floats2bfloat162_rn(fmaxf(cr[nt][2], 0.0f), fmaxf(cr[nt][3], 0.0f));
                Xrw[(mrow + g + 8) * RS + cw] = *(uint32_t*)&hh;
                hh = __floats2bfloat162_rn(fmaxf(ci[nt][0], 0.0f), fmaxf(ci[nt][1], 0.0f));
                Xiw[(mrow + g) * RS + cw] = *(uint32_t*)&hh;
                hh = __floats2bfloat162_rn(fmaxf(ci[nt][2], 0.0f), fmaxf(ci[nt][3], 0.0f));
                Xiw[(mrow + g + 8) * RS + cw] = *(uint32_t*)&hh;
            }
        }
        __syncwarp();

        // ---------- layer 2 ----------
        #pragma unroll
        for (int nt = 0; nt < 12; nt++) {
            float br0 = s_bv[192 + nt * 8 + 2 * t], br1 = s_bv[192 + nt * 8 + 2 * t + 1];
            float bi0 = s_bv[288 + nt * 8 + 2 * t], bi1 = s_bv[288 + nt * 8 + 2 * t + 1];
            cr[nt][0] = br0; cr[nt][1] = br1; cr[nt][2] = br0; cr[nt][3] = br1;
            ci[nt][0] = bi0; ci[nt][1] = bi1; ci[nt][2] = bi0; ci[nt][3] = bi1;
        }
        #pragma unroll
        for (int k = 0; k < 6; k++) {
            int kw = k * 8 + t;
            uint32_t ar[4], ai[4];
            ar[0] = Xr[(mrow + g) * RS + kw];     ar[1] = Xr[(mrow + g + 8) * RS + kw];
            ar[2] = Xr[(mrow + g) * RS + kw + 4]; ar[3] = Xr[(mrow + g + 8) * RS + kw + 4];
            ai[0] = Xi[(mrow + g) * RS + kw];     ai[1] = Xi[(mrow + g + 8) * RS + kw];
            ai[2] = Xi[(mrow + g) * RS + kw + 4]; ai[3] = Xi[(mrow + g + 8) * RS + kw + 4];
            #pragma unroll
            for (int nt = 0; nt < 12; nt++) {
                int wrow = (nt * 8 + g) * RS + kw;
                uint32_t wr0  = Ww[3 * 96 * RS + wrow], wr1  = Ww[3 * 96 * RS + wrow + 4];
                uint32_t wi0  = Ww[4 * 96 * RS + wrow], wi1  = Ww[4 * 96 * RS + wrow + 4];
                uint32_t nwi0 = Ww[5 * 96 * RS + wrow], nwi1 = Ww[5 * 96 * RS + wrow + 4];
                mma_bf16(cr[nt], ar, wr0, wr1);
                mma_bf16(cr[nt], ai, nwi0, nwi1);
                mma_bf16(ci[nt], ai, wr0, wr1);
                mma_bf16(ci[nt], ar, wi0, wi1);
            }
        }

        // ---------- softshrink + store ----------
        int mode_lo = m0 + mrow + g;
        int mode_hi = mode_lo + 8;
        #pragma unroll
        for (int nt = 0; nt < 12; nt++) {
            #pragma unroll
            for (int j = 0; j < 4; j++) {
                int col  = nt * 8 + 2 * t + (j & 1);
                int mode = (j < 2) ? mode_lo : mode_hi;
                if (mode < MODES) {
                    size_t off = rowbase + (size_t)col * MODES + mode;
                    float vr = cr[nt][j];
                    float vi = ci[nt][j];
                    g_Xre[off] = copysignf(fmaxf(fabsf(vr) - LAM, 0.0f), vr);
                    g_Xim[off] = copysignf(fmaxf(fabsf(vi) - LAM, 0.0f), vi);
                }
            }
        }
    }
}

// ---------------- inverse rfft: X planar -> yT[b*CH+c][s] -------------------
__global__ void __launch_bounds__(256, 2) inv_fft_kernel() {
    extern __shared__ char smraw[];
    float2* A = (float2*)smraw;
    float2* B = A + FFT_BUF;
    int row = blockIdx.x;
    const float* Xre = g_Xre + (size_t)row * MODES;
    const float* Xim = g_Xim + (size_t)row * MODES;
    for (int k = threadIdx.x; k < 4096; k += 256) {
        float xkr = Xre[k],        xki = Xim[k];
        float xcr = Xre[4096 - k], xci = Xim[4096 - k];
        if (k == 0) { xki = 0.0f; xci = 0.0f; }
        float Ex = 0.5f * (xkr + xcr), Ey = 0.5f * (xki - xci);
        float Gx = 0.5f * (xkr - xcr), Gy = 0.5f * (xki + xci);
        float2 w = g_wr[k];
        float WOx = w.x * Gx - w.y * Gy;
        float WOy = w.x * Gy + w.y * Gx;
        float Zx = Ex - WOy;
        float Zy = Ey + WOx;
        A[IX(k)] = make_float2(INV_SCALE * Zx, -INV_SCALE * Zy);
    }
    __syncthreads();
    float2* R = fft4096_r16(A, B);
    float2* out = (float2*)(g_yT + (size_t)row * SEQ);
    for (int j = threadIdx.x; j < 4096; j += 256) {
        float2 r = R[IX(j)];
        out[j] = make_float2(r.x, -r.y);
    }
}

// ---------------- transpose + bias: out[b,s,c] = x[b,s,c] + yT[b,c,s] -------
__global__ void __launch_bounds__(256) final_kernel(const float* __restrict__ x,
                                                    float* __restrict__ out) {
    __shared__ float t[32][33];
    int b  = blockIdx.z;
    int c0 = blockIdx.x * 32;
    int s0 = blockIdx.y * 32;
    int tx = threadIdx.x, ty = threadIdx.y;
    #pragma unroll
    for (int i = 0; i < 4; i++) {
        int cc = c0 + ty + 8 * i;
        t[ty + 8 * i][tx] = g_yT[((size_t)b * CH + cc) * SEQ + s0 + tx];
    }
    __syncthreads();
    #pragma unroll
    for (int i = 0; i < 4; i++) {
        int s = s0 + ty + 8 * i;
        size_t off = ((size_t)b * SEQ + s) * CH + c0 + tx;
        out[off] = x[off] + t[tx][ty + 8 * i];
    }
}

// ---------------- launcher ----------------
extern "C" void kernel_launch(void* const* d_in, const int* in_sizes, int n_in,
                              void* d_out, int out_size) {
    const float* x  = (const float*)d_in[0];
    const float* w1 = (const float*)d_in[1];
    const float* b1 = (const float*)d_in[2];
    const float* w2 = (const float*)d_in[3];
    const float* b2 = (const float*)d_in[4];
    float* out = (float*)d_out;

    cudaFuncSetAttribute(fwd_fft_kernel, cudaFuncAttributeMaxDynamicSharedMemorySize, FFT_SMEM);
    cudaFuncSetAttribute(inv_fft_kernel, cudaFuncAttributeMaxDynamicSharedMemorySize, FFT_SMEM);
    cudaFuncSetAttribute(mlp_mma_kernel, cudaFuncAttributeMaxDynamicSharedMemorySize, MLP_SMEM);

    init_tables_kernel<<<17, 256>>>();
    fwd_fft_kernel<<<BATCH * CH, 256, FFT_SMEM>>>(x);
    mlp_mma_kernel<<<dim3((MODES + MT - 1) / MT, NBLK, BATCH), 256, MLP_SMEM>>>(w1, b1, w2, b2);
    inv_fft_kernel<<<BATCH * CH, 256, FFT_SMEM>>>();
    final_kernel<<<dim3(CH / 32, SEQ / 32, BATCH), dim3(32, 8)>>>(x, out);
}